// round 15
// baseline (speedup 1.0000x reference)
#include <cuda_runtime.h>
#include <cuda_bf16.h>
#include <cuda_fp16.h>
#include <math.h>
#include <stdint.h>

#define SEQ    2048
#define DM     768
#define NL     4
#define DSTATE 128
#define HD     64
#define NCH    32
#define DIN    1536
#define NH     24
#define CONVD  1792
#define DPROJ  3352
#define NV     50288

// ---------------- scratch (device globals) ----------------
__device__ __align__(128) float g_x[SEQ*DM];
__device__ __align__(128) float g_zx[SEQ*DPROJ];
__device__ __align__(128) float g_xBC[SEQ*CONVD];
__device__ __align__(128) float g_dt[SEQ*NH];
__device__ __align__(128) float g_acs[SEQ*NH];
__device__ __align__(128) float g_Aexp[NCH*NH];
__device__ __align__(128) float g_cb[NCH*64*64];       // [c][i][j] = CB[i][j]
__device__ __align__(128) float g_states[NCH*NH*HD*DSTATE];
__device__ __align__(128) float g_y[SEQ*DIN];

// bf16 split operands (in_proj, 3-term)
__device__ __align__(128) __nv_bfloat16 g_inwh[NL*DPROJ*DM];
__device__ __align__(128) __nv_bfloat16 g_inwl[NL*DPROJ*DM];
__device__ __align__(128) __nv_bfloat16 g_uh[SEQ*DM];
__device__ __align__(128) __nv_bfloat16 g_ul[SEQ*DM];

// fp16 operands (out_proj 2-term, logits 1-term)
__device__ __align__(128) __half g_owh16[NL*DM*DIN];
__device__ __align__(128) __half g_owl16[NL*DM*DIN];
__device__ __align__(128) __half g_yn16[SEQ*DIN];
__device__ __align__(128) __half g_embh[NV*DM];
__device__ __align__(128) __half g_u16[SEQ*DM];

// ---------------- PTX helpers ----------------
__device__ __forceinline__ uint32_t smem_u32(const void* p) {
    uint32_t a;
    asm("{ .reg .u64 t; cvta.to.shared.u64 t, %1; cvt.u32.u64 %0, t; }" : "=r"(a) : "l"(p));
    return a;
}
__device__ __forceinline__ void cpa16(uint32_t dst, const void* src) {
    asm volatile("cp.async.cg.shared.global [%0], [%1], 16;" :: "r"(dst), "l"(src) : "memory");
}
#define CP_COMMIT() asm volatile("cp.async.commit_group;" ::: "memory")
#define CP_WAIT(n)  asm volatile("cp.async.wait_group %0;" :: "n"(n) : "memory")

__device__ __forceinline__ void ldsm4(uint32_t addr, uint32_t& r0, uint32_t& r1,
                                      uint32_t& r2, uint32_t& r3) {
    asm volatile("ldmatrix.sync.aligned.m8n8.x4.shared.b16 {%0,%1,%2,%3}, [%4];"
                 : "=r"(r0), "=r"(r1), "=r"(r2), "=r"(r3) : "r"(addr));
}
__device__ __forceinline__ void mma_bf16(float* d, const uint32_t* a, const uint32_t* b) {
    asm volatile(
        "mma.sync.aligned.m16n8k16.row.col.f32.bf16.bf16.f32 "
        "{%0,%1,%2,%3}, {%4,%5,%6,%7}, {%8,%9}, {%0,%1,%2,%3};"
        : "+f"(d[0]), "+f"(d[1]), "+f"(d[2]), "+f"(d[3])
        : "r"(a[0]), "r"(a[1]), "r"(a[2]), "r"(a[3]), "r"(b[0]), "r"(b[1]));
}
__device__ __forceinline__ void mma_f16(float* d, const uint32_t* a, const uint32_t* b) {
    asm volatile(
        "mma.sync.aligned.m16n8k16.row.col.f32.f16.f16.f32 "
        "{%0,%1,%2,%3}, {%4,%5,%6,%7}, {%8,%9}, {%0,%1,%2,%3};"
        : "+f"(d[0]), "+f"(d[1]), "+f"(d[2]), "+f"(d[3])
        : "r"(a[0]), "r"(a[1]), "r"(a[2]), "r"(a[3]), "r"(b[0]), "r"(b[1]));
}
__device__ __forceinline__ void split_bf16(float v, __nv_bfloat16& h, __nv_bfloat16& l) {
    h = __float2bfloat16(v);
    l = __float2bfloat16(v - __bfloat162float(h));
}

#define RS 80
#define A_BYTES (128*RS)              // 10240

// ================= split-bf16 3-term GEMM, 128x128, 3-stage (in_proj) ========
#define SLABB     (4*A_BYTES)         // 40960
#define GEMM_SMEM (3*SLABB)           // 122880

__global__ void __launch_bounds__(256, 1)
gemm_tc(const __nv_bfloat16* __restrict__ Ah, const __nv_bfloat16* __restrict__ Al,
        const __nv_bfloat16* __restrict__ Bh, const __nv_bfloat16* __restrict__ Bl,
        float* __restrict__ C, int M, int N, int K) {
    extern __shared__ char dsm[];
    const uint32_t sbase = smem_u32(dsm);
    const int tid = threadIdx.x, wid = tid >> 5, lane = tid & 31;
    const int m0 = blockIdx.x * 128, n0 = blockIdx.y * 128;
    const int nslab = K >> 5;
    const int mw = (wid & 1) * 64, nw = (wid >> 1) * 32;

    float acc[4][4][4];
#pragma unroll
    for (int i = 0; i < 4; i++)
#pragma unroll
        for (int j = 0; j < 4; j++)
#pragma unroll
            for (int k = 0; k < 4; k++) acc[i][j][k] = 0.f;

    auto load_slab = [&](int s, int b) {
        const int k0 = s << 5;
        const uint32_t base = sbase + b * SLABB;
#pragma unroll
        for (int t = 0; t < 2; t++) {
            int idx = tid + t * 256;
            int r = idx >> 2, c = idx & 3;
            uint32_t d = base + r * RS + c * 16;
            size_t g = (size_t)(m0 + r) * K + k0 + c * 8;
            cpa16(d, Ah + g);
            cpa16(d + A_BYTES, Al + g);
        }
#pragma unroll
        for (int t = 0; t < 2; t++) {
            int idx = tid + t * 256;
            int r = idx >> 2, c = idx & 3;
            int rn = n0 + r; if (rn > N - 1) rn = N - 1;
            uint32_t d = base + 2 * A_BYTES + r * RS + c * 16;
            size_t g = (size_t)rn * K + k0 + c * 8;
            cpa16(d, Bh + g);
            cpa16(d + A_BYTES, Bl + g);
        }
    };

    load_slab(0, 0);
    CP_COMMIT();
    if (nslab > 1) { load_slab(1, 1); CP_COMMIT(); }

    int buf = 0;
    for (int s = 0; s < nslab; s++) {
        if (s + 2 < nslab) {
            int b2 = (s + 2) % 3;
            load_slab(s + 2, b2);
            CP_COMMIT();
            CP_WAIT(2);
        } else if (s + 1 < nslab) {
            CP_WAIT(1);
        } else {
            CP_WAIT(0);
        }
        __syncthreads();

        const uint32_t abase = sbase + buf * SLABB;
        const uint32_t bbase = abase + 2 * A_BYTES;
#pragma unroll
        for (int ks = 0; ks < 2; ks++) {
            uint32_t a_h[4][4], a_l[4][4], b_h[4][2], b_l[4][2];
#pragma unroll
            for (int mi = 0; mi < 4; mi++) {
                uint32_t ad = abase + (mw + mi * 16 + (lane & 15)) * RS
                            + ((lane >> 4) << 4) + ks * 32;
                ldsm4(ad, a_h[mi][0], a_h[mi][1], a_h[mi][2], a_h[mi][3]);
                ldsm4(ad + A_BYTES, a_l[mi][0], a_l[mi][1], a_l[mi][2], a_l[mi][3]);
            }
#pragma unroll
            for (int nb = 0; nb < 2; nb++) {
                uint32_t bd = bbase + (nw + nb * 16 + ((lane >> 4) << 3) + (lane & 7)) * RS
                            + (((lane >> 3) & 1) << 4) + ks * 32;
                uint32_t r0, r1, r2, r3;
                ldsm4(bd, r0, r1, r2, r3);
                b_h[2*nb][0] = r0; b_h[2*nb][1] = r1;
                b_h[2*nb+1][0] = r2; b_h[2*nb+1][1] = r3;
                ldsm4(bd + A_BYTES, r0, r1, r2, r3);
                b_l[2*nb][0] = r0; b_l[2*nb][1] = r1;
                b_l[2*nb+1][0] = r2; b_l[2*nb+1][1] = r3;
            }
#pragma unroll
            for (int mi = 0; mi < 4; mi++)
#pragma unroll
                for (int ni = 0; ni < 4; ni++)
                    mma_bf16(acc[mi][ni], a_h[mi], b_h[ni]);
#pragma unroll
            for (int mi = 0; mi < 4; mi++)
#pragma unroll
                for (int ni = 0; ni < 4; ni++)
                    mma_bf16(acc[mi][ni], a_h[mi], b_l[ni]);
#pragma unroll
            for (int mi = 0; mi < 4; mi++)
#pragma unroll
                for (int ni = 0; ni < 4; ni++)
                    mma_bf16(acc[mi][ni], a_l[mi], b_h[ni]);
        }
        __syncthreads();
        buf = (buf + 1) % 3;
    }

#pragma unroll
    for (int mi = 0; mi < 4; mi++) {
#pragma unroll
        for (int half = 0; half < 2; half++) {
            int m = m0 + mw + mi * 16 + (lane >> 2) + half * 8;
#pragma unroll
            for (int ni = 0; ni < 4; ni++) {
                int n = n0 + nw + ni * 8 + 2 * (lane & 3);
                if (n < N) {
                    float* p = C + (size_t)m * N + n;
                    p[0] = acc[mi][ni][half*2];
                    p[1] = acc[mi][ni][half*2+1];
                }
            }
        }
    }
}

// ================= fp16 1-term GEMM, 128x128, 3-stage (logits) ===============
#define SLABH      (2*A_BYTES)        // 20480
#define GEMMH_SMEM (3*SLABH)          // 61440

__global__ void __launch_bounds__(256, 2)
gemm_half(const __half* __restrict__ A, const __half* __restrict__ B,
          float* __restrict__ C, int M, int N, int K) {
    extern __shared__ char dsm[];
    const uint32_t sbase = smem_u32(dsm);
    const int tid = threadIdx.x, wid = tid >> 5, lane = tid & 31;
    const int m0 = blockIdx.x * 128, n0 = blockIdx.y * 128;
    const int nslab = K >> 5;
    const int mw = (wid & 1) * 64, nw = (wid >> 1) * 32;

    float acc[4][4][4];
#pragma unroll
    for (int i = 0; i < 4; i++)
#pragma unroll
        for (int j = 0; j < 4; j++)
#pragma unroll
            for (int k = 0; k < 4; k++) acc[i][j][k] = 0.f;

    auto load_slab = [&](int s, int b) {
        const int k0 = s << 5;
        const uint32_t base = sbase + b * SLABH;
#pragma unroll
        for (int t = 0; t < 2; t++) {
            int idx = tid + t * 256;
            int r = idx >> 2, c = idx & 3;
            uint32_t d = base + r * RS + c * 16;
            cpa16(d, A + (size_t)(m0 + r) * K + k0 + c * 8);
            int rn = n0 + r; if (rn > N - 1) rn = N - 1;
            cpa16(d + A_BYTES, B + (size_t)rn * K + k0 + c * 8);
        }
    };

    load_slab(0, 0);
    CP_COMMIT();
    if (nslab > 1) { load_slab(1, 1); CP_COMMIT(); }

    int buf = 0;
    for (int s = 0; s < nslab; s++) {
        if (s + 2 < nslab) {
            load_slab(s + 2, (s + 2) % 3);
            CP_COMMIT();
            CP_WAIT(2);
        } else if (s + 1 < nslab) {
            CP_WAIT(1);
        } else {
            CP_WAIT(0);
        }
        __syncthreads();

        const uint32_t abase = sbase + buf * SLABH;
        const uint32_t bbase = abase + A_BYTES;
#pragma unroll
        for (int ks = 0; ks < 2; ks++) {
            uint32_t a_f[4][4], b_f[4][2];
#pragma unroll
            for (int mi = 0; mi < 4; mi++) {
                uint32_t ad = abase + (mw + mi * 16 + (lane & 15)) * RS
                            + ((lane >> 4) << 4) + ks * 32;
                ldsm4(ad, a_f[mi][0], a_f[mi][1], a_f[mi][2], a_f[mi][3]);
            }
#pragma unroll
            for (int nb = 0; nb < 2; nb++) {
                uint32_t bd = bbase + (nw + nb * 16 + ((lane >> 4) << 3) + (lane & 7)) * RS
                            + (((lane >> 3) & 1) << 4) + ks * 32;
                uint32_t r0, r1, r2, r3;
                ldsm4(bd, r0, r1, r2, r3);
                b_f[2*nb][0] = r0; b_f[2*nb][1] = r1;
                b_f[2*nb+1][0] = r2; b_f[2*nb+1][1] = r3;
            }
#pragma unroll
            for (int mi = 0; mi < 4; mi++)
#pragma unroll
                for (int ni = 0; ni < 4; ni++)
                    mma_f16(acc[mi][ni], a_f[mi], b_f[ni]);
        }
        __syncthreads();
        buf = (buf + 1) % 3;
    }

#pragma unroll
    for (int mi = 0; mi < 4; mi++) {
#pragma unroll
        for (int half = 0; half < 2; half++) {
            int m = m0 + mw + mi * 16 + (lane >> 2) + half * 8;
#pragma unroll
            for (int ni = 0; ni < 4; ni++) {
                int n = n0 + nw + ni * 8 + 2 * (lane & 3);
                if (n < N) {
                    float* p = C + (size_t)m * N + n;
                    p[0] = acc[mi][ni][half*2];
                    p[1] = acc[mi][ni][half*2+1];
                }
            }
        }
    }
}

// ================= fp16 2-term GEMM, 128x128, 3-stage (out_proj) =============
#define SLAB2      (3*A_BYTES)        // 30720
#define GEMM2_SMEM (3*SLAB2)          // 92160

__global__ void __launch_bounds__(256, 2)
gemm_half2(const __half* __restrict__ A, const __half* __restrict__ Bh,
           const __half* __restrict__ Bl, const float* __restrict__ addsrc,
           float* __restrict__ C, int M, int N, int K) {
    extern __shared__ char dsm[];
    const uint32_t sbase = smem_u32(dsm);
    const int tid = threadIdx.x, wid = tid >> 5, lane = tid & 31;
    const int m0 = blockIdx.x * 128, n0 = blockIdx.y * 128;
    const int nslab = K >> 5;
    const int mw = (wid & 1) * 64, nw = (wid >> 1) * 32;

    float acc[4][4][4];
#pragma unroll
    for (int i = 0; i < 4; i++)
#pragma unroll
        for (int j = 0; j < 4; j++)
#pragma unroll
            for (int k = 0; k < 4; k++) acc[i][j][k] = 0.f;

    auto load_slab = [&](int s, int b) {
        const int k0 = s << 5;
        const uint32_t base = sbase + b * SLAB2;
#pragma unroll
        for (int t = 0; t < 2; t++) {
            int idx = tid + t * 256;
            int r = idx >> 2, c = idx & 3;
            uint32_t d = base + r * RS + c * 16;
            cpa16(d, A + (size_t)(m0 + r) * K + k0 + c * 8);
            int rn = n0 + r; if (rn > N - 1) rn = N - 1;
            size_t g = (size_t)rn * K + k0 + c * 8;
            cpa16(d + A_BYTES, Bh + g);
            cpa16(d + 2 * A_BYTES, Bl + g);
        }
    };

    load_slab(0, 0);
    CP_COMMIT();
    if (nslab > 1) { load_slab(1, 1); CP_COMMIT(); }

    int buf = 0;
    for (int s = 0; s < nslab; s++) {
        if (s + 2 < nslab) {
            load_slab(s + 2, (s + 2) % 3);
            CP_COMMIT();
            CP_WAIT(2);
        } else if (s + 1 < nslab) {
            CP_WAIT(1);
        } else {
            CP_WAIT(0);
        }
        __syncthreads();

        const uint32_t abase = sbase + buf * SLAB2;
        const uint32_t bbase = abase + A_BYTES;
#pragma unroll
        for (int ks = 0; ks < 2; ks++) {
            uint32_t a_f[4][4], b_h[4][2], b_l[4][2];
#pragma unroll
            for (int mi = 0; mi < 4; mi++) {
                uint32_t ad = abase + (mw + mi * 16 + (lane & 15)) * RS
                            + ((lane >> 4) << 4) + ks * 32;
                ldsm4(ad, a_f[mi][0], a_f[mi][1], a_f[mi][2], a_f[mi][3]);
            }
#pragma unroll
            for (int nb = 0; nb < 2; nb++) {
                uint32_t bd = bbase + (nw + nb * 16 + ((lane >> 4) << 3) + (lane & 7)) * RS
                            + (((lane >> 3) & 1) << 4) + ks * 32;
                uint32_t r0, r1, r2, r3;
                ldsm4(bd, r0, r1, r2, r3);
                b_h[2*nb][0] = r0; b_h[2*nb][1] = r1;
                b_h[2*nb+1][0] = r2; b_h[2*nb+1][1] = r3;
                ldsm4(bd + A_BYTES, r0, r1, r2, r3);
                b_l[2*nb][0] = r0; b_l[2*nb][1] = r1;
                b_l[2*nb+1][0] = r2; b_l[2*nb+1][1] = r3;
            }
#pragma unroll
            for (int mi = 0; mi < 4; mi++)
#pragma unroll
                for (int ni = 0; ni < 4; ni++)
                    mma_f16(acc[mi][ni], a_f[mi], b_h[ni]);
#pragma unroll
            for (int mi = 0; mi < 4; mi++)
#pragma unroll
                for (int ni = 0; ni < 4; ni++)
                    mma_f16(acc[mi][ni], a_f[mi], b_l[ni]);
        }
        __syncthreads();
        buf = (buf + 1) % 3;
    }

#pragma unroll
    for (int mi = 0; mi < 4; mi++) {
#pragma unroll
        for (int half = 0; half < 2; half++) {
            int m = m0 + mw + mi * 16 + (lane >> 2) + half * 8;
#pragma unroll
            for (int ni = 0; ni < 4; ni++) {
                int n = n0 + nw + ni * 8 + 2 * (lane & 3);
                if (n < N) {
                    float2 v = make_float2(acc[mi][ni][half*2], acc[mi][ni][half*2+1]);
                    const float* q = addsrc + (size_t)m * N + n;
                    v.x += q[0]; v.y += q[1];
                    float* p = C + (size_t)m * N + n;
                    p[0] = v.x; p[1] = v.y;
                }
            }
        }
    }
}

// ---------------- misc kernels ----------------
__device__ __forceinline__ float block_sum(float v) {
    __shared__ float red[256];
    int t = threadIdx.x;
    red[t] = v; __syncthreads();
    for (int s = 128; s > 0; s >>= 1) {
        if (t < s) red[t] += red[t + s];
        __syncthreads();
    }
    float r = red[0];
    __syncthreads();
    return r;
}

__global__ void embed_kernel(const int* __restrict__ ids, const float* __restrict__ emb) {
    int l = blockIdx.x;
    int id = ids[l];
    const float4* src = (const float4*)(emb + (size_t)id*DM);
    float4* dst = (float4*)(g_x + (size_t)l*DM);
    for (int d = threadIdx.x; d < DM/4; d += 256)
        dst[d] = src[d];
}

__global__ void split_kernel(const float* __restrict__ s, __nv_bfloat16* __restrict__ h,
                             __nv_bfloat16* __restrict__ l, int n4) {
    int i = blockIdx.x*256 + threadIdx.x;
    if (i >= n4) return;
    float4 v = ((const float4*)s)[i];
    __nv_bfloat16 h0 = __float2bfloat16(v.x), h1 = __float2bfloat16(v.y);
    __nv_bfloat16 h2 = __float2bfloat16(v.z), h3 = __float2bfloat16(v.w);
    h[i*4+0] = h0; h[i*4+1] = h1; h[i*4+2] = h2; h[i*4+3] = h3;
    l[i*4+0] = __float2bfloat16(v.x - __bfloat162float(h0));
    l[i*4+1] = __float2bfloat16(v.y - __bfloat162float(h1));
    l[i*4+2] = __float2bfloat16(v.z - __bfloat162float(h2));
    l[i*4+3] = __float2bfloat16(v.w - __bfloat162float(h3));
}

__global__ void split_half_kernel(const float* __restrict__ s, __half* __restrict__ h,
                                  __half* __restrict__ l, int n) {
    int i = blockIdx.x*256 + threadIdx.x;
    if (i >= n) return;
    float v = s[i];
    __half hv = __float2half(v);
    h[i] = hv;
    l[i] = __float2half(v - __half2float(hv));
}

__global__ void convert_half_kernel(const float* __restrict__ s, __half* __restrict__ d, int n4) {
    int i = blockIdx.x*256 + threadIdx.x;
    if (i >= n4) return;
    float4 v = ((const float4*)s)[i];
    ((__half2*)d)[i*2]   = __floats2half2_rn(v.x, v.y);
    ((__half2*)d)[i*2+1] = __floats2half2_rn(v.z, v.w);
}

__global__ void rmsnorm_split_kernel(const float* __restrict__ in, const float* __restrict__ w,
                                     __nv_bfloat16* __restrict__ oh, __nv_bfloat16* __restrict__ ol) {
    int row = blockIdx.x;
    const float* x = in + (size_t)row*DM;
    float s = 0.f;
    for (int i = threadIdx.x; i < DM; i += 256) { float v = x[i]; s += v*v; }
    float tot = block_sum(s);
    float sc = rsqrtf(tot / (float)DM + 1e-5f);
    for (int i = threadIdx.x; i < DM; i += 256) {
        float v = x[i] * sc * w[i];
        __nv_bfloat16 h = __float2bfloat16(v);
        oh[(size_t)row*DM + i] = h;
        ol[(size_t)row*DM + i] = __float2bfloat16(v - __bfloat162float(h));
    }
}

__global__ void rmsnorm_half_kernel(const float* __restrict__ in, const float* __restrict__ w,
                                    __half* __restrict__ out) {
    int row = blockIdx.x;
    const float* x = in + (size_t)row*DM;
    float s = 0.f;
    for (int i = threadIdx.x; i < DM; i += 256) { float v = x[i]; s += v*v; }
    float tot = block_sum(s);
    float sc = rsqrtf(tot / (float)DM + 1e-5f);
    for (int i = threadIdx.x; i < DM; i += 256)
        out[(size_t)row*DM + i] = __float2half(x[i] * sc * w[i]);
}

__global__ void gated_rmsnorm_kernel(const float* __restrict__ w) {
    int row = blockIdx.x;
    __shared__ float tbuf[DIN];
    float s = 0.f;
    for (int i = threadIdx.x; i < DIN; i += 256) {
        float v = g_y[(size_t)row*DIN + i];
        float z = g_zx[(size_t)row*DPROJ + i];
        float g = v * (z / (1.f + __expf(-z)));
        tbuf[i] = g; s += g*g;
    }
    float tot = block_sum(s);
    float sc = rsqrtf(tot / (float)DIN + 1e-5f);
    for (int i = threadIdx.x; i < DIN; i += 256)
        g_yn16[(size_t)row*DIN + i] = __float2half(tbuf[i] * sc * w[i]);
}

// conv (blocks 0..3583) fused with dtacs (blocks 3584..3679); both depend only on g_zx
#define CONV_BLKS (SEQ*(CONVD/4)/256)   // 3584
__global__ void __launch_bounds__(256)
conv_dtacs_kernel(const float* __restrict__ cw, const float* __restrict__ cb,
                  const float* __restrict__ dtb, const float* __restrict__ alog) {
    if (blockIdx.x < CONV_BLKS) {
        int idx = blockIdx.x*256 + threadIdx.x;
        const int C4 = CONVD/4;
        int l = idx / C4, ch4 = (idx % C4) * 4;

        float4 bias = *(const float4*)(cb + ch4);
        float s0 = bias.x, s1 = bias.y, s2 = bias.z, s3 = bias.w;
        float4 w0 = *(const float4*)(cw + ch4*4);
        float4 w1 = *(const float4*)(cw + ch4*4 + 4);
        float4 w2 = *(const float4*)(cw + ch4*4 + 8);
        float4 w3 = *(const float4*)(cw + ch4*4 + 12);
        const float wa[4][4] = {{w0.x,w0.y,w0.z,w0.w},{w1.x,w1.y,w1.z,w1.w},
                                {w2.x,w2.y,w2.z,w2.w},{w3.x,w3.y,w3.z,w3.w}};
#pragma unroll
        for (int k = 0; k < 4; k++) {
            int t = l - 3 + k;
            if (t >= 0) {
                float4 xz = *(const float4*)(g_zx + (size_t)t*DPROJ + DIN + ch4);
                s0 += wa[0][k]*xz.x; s1 += wa[1][k]*xz.y;
                s2 += wa[2][k]*xz.z; s3 += wa[3][k]*xz.w;
            }
        }
        float4 o;
        o.x = s0 / (1.f + __expf(-s0));
        o.y = s1 / (1.f + __expf(-s1));
        o.z = s2 / (1.f + __expf(-s2));
        o.w = s3 / (1.f + __expf(-s3));
        *(float4*)(g_xBC + (size_t)l*CONVD + ch4) = o;
    } else {
        // dtacs: b in [0,96): c = b & 31, y = b >> 5; h = y*8 + warp
        int b = blockIdx.x - CONV_BLKS;
        int wid = threadIdx.x >> 5, lane = threadIdx.x & 31;
        int h = (b >> 5) * 8 + wid;
        int c = b & 31;
        int l0 = c * 64 + lane * 2;

        float bias = dtb[h];
        float Aneg = -expf(alog[h]);
        float v0 = g_zx[(size_t)l0*DPROJ + DIN + CONVD + h] + bias;
        float v1 = g_zx[(size_t)(l0+1)*DPROJ + DIN + CONVD + h] + bias;
        float dt0 = (v0 > 20.f) ? v0 : log1pf(expf(v0));
        float dt1 = (v1 > 20.f) ? v1 : log1pf(expf(v1));
        g_dt[l0*NH + h] = dt0;
        g_dt[(l0+1)*NH + h] = dt1;
        float a0 = Aneg * dt0, a1 = Aneg * dt1;
        float pair = a0 + a1;
        float s = pair;
#pragma unroll
        for (int o = 1; o < 32; o <<= 1) {
            float t = __shfl_up_sync(0xFFFFFFFFu, s, o);
            if (lane >= o) s += t;
        }
        float excl = s - pair;
        g_acs[l0*NH + h] = excl + a0;
        g_acs[(l0+1)*NH + h] = excl + a0 + a1;
        if (lane == 31) g_Aexp[c*NH + h] = expf(s);
    }
}

// head-shared CB[c][i][j]
#define CB_SMEM (2*64*129*4)
__global__ void __launch_bounds__(256)
cb_kernel() {
    extern __shared__ char dsm[];
    float* sB = (float*)dsm;
    float* sC = sB + 64*129;
    const int c = blockIdx.x, tid = threadIdx.x;

    for (int idx = tid; idx < 64*128; idx += 256) {
        int r = idx >> 7, n = idx & 127;
        const float* row = g_xBC + (size_t)(c*64 + r)*CONVD + DIN;
        sB[r*129 + n] = row[n];
        sC[r*129 + n] = row[DSTATE + n];
    }
    __syncthreads();

    const int i0 = (tid & 15)*4, j0 = (tid >> 4)*4;
    float acc[4][4] = {};
    for (int n = 0; n < 128; n++) {
        float a[4], b[4];
#pragma unroll
        for (int ii = 0; ii < 4; ii++) a[ii] = sC[(i0+ii)*129 + n];
#pragma unroll
        for (int jj = 0; jj < 4; jj++) b[jj] = sB[(j0+jj)*129 + n];
#pragma unroll
        for (int ii = 0; ii < 4; ii++)
#pragma unroll
            for (int jj = 0; jj < 4; jj++) acc[ii][jj] += a[ii]*b[jj];
    }
#pragma unroll
    for (int ii = 0; ii < 4; ii++)
#pragma unroll
        for (int jj = 0; jj < 4; jj++)
            g_cb[c*4096 + (i0+ii)*64 + j0 + jj] = acc[ii][jj];
}

// ============ TENSOR-CORE chunk =========
#define CK_MH   0
#define CK_ML   9216
#define CK_XH   18432
#define CK_XL   27648
#define CK_BH   36864
#define CK_BL   55296
#define CK_ACS  73728
#define CK_DEC  73984
#define CHUNK_SMEM 74240

__global__ void __launch_bounds__(256)
chunk_kernel() {
    extern __shared__ char dsm[];
    __nv_bfloat16* sMh = (__nv_bfloat16*)(dsm + CK_MH);
    __nv_bfloat16* sMl = (__nv_bfloat16*)(dsm + CK_ML);
    __nv_bfloat16* sXh = (__nv_bfloat16*)(dsm + CK_XH);
    __nv_bfloat16* sXl = (__nv_bfloat16*)(dsm + CK_XL);
    __nv_bfloat16* sBh = (__nv_bfloat16*)(dsm + CK_BH);
    __nv_bfloat16* sBl = (__nv_bfloat16*)(dsm + CK_BL);
    float* sAcs = (float*)(dsm + CK_ACS);
    float* sDec = (float*)(dsm + CK_DEC);
    const uint32_t sbase = smem_u32(dsm);

    const int c = blockIdx.x, h = blockIdx.y, tid = threadIdx.x;
    const int w = tid >> 5, lane = tid & 31;

    if (tid < 64) sAcs[tid] = g_acs[(c*64 + tid)*NH + h];
    __syncthreads();
    if (tid < 64) sDec[tid] = __expf(sAcs[63] - sAcs[tid]);
    __syncthreads();

    for (int idx = tid; idx < 64*64; idx += 256) {
        int j = idx >> 6, p = idx & 63;
        float v = g_xBC[(size_t)(c*64 + j)*CONVD + h*HD + p] * g_dt[(c*64 + j)*NH + h];
        split_bf16(v, sXh[p*72 + j], sXl[p*72 + j]);
    }
    for (int idx = tid; idx < 64*64; idx += 256) {
        int i = idx >> 6, j = idx & 63;
        float v = (j <= i) ? g_cb[c*4096 + idx] * __expf(sAcs[i] - sAcs[j]) : 0.f;
        split_bf16(v, sMh[i*72 + j], sMl[i*72 + j]);
    }
    for (int idx = tid; idx < 64*128; idx += 256) {
        int j = idx >> 7, n = idx & 127;
        float v = g_xBC[(size_t)(c*64 + j)*CONVD + DIN + n] * sDec[j];
        split_bf16(v, sBh[n*72 + j], sBl[n*72 + j]);
    }
    __syncthreads();

    const uint32_t aM = sbase + CK_MH, aX = sbase + CK_XH, aB = sbase + CK_BH;

    {   // Y_diag
        const int mB = (w & 3) * 16, nB = (w >> 2) * 32;
        float acc[4][4] = {};
#pragma unroll
        for (int ks = 0; ks < 4; ks++) {
            uint32_t a_h[4], a_l[4], b_h[4][2], b_l[4][2];
            uint32_t ad = aM + (mB + (lane & 15)) * 144 + ((lane >> 4) << 4) + ks * 32;
            ldsm4(ad, a_h[0], a_h[1], a_h[2], a_h[3]);
            ldsm4(ad + 9216, a_l[0], a_l[1], a_l[2], a_l[3]);
#pragma unroll
            for (int nb = 0; nb < 2; nb++) {
                uint32_t bd = aX + (nB + nb*16 + ((lane >> 4) << 3) + (lane & 7)) * 144
                            + (((lane >> 3) & 1) << 4) + ks * 32;
                uint32_t r0, r1, r2, r3;
                ldsm4(bd, r0, r1, r2, r3);
                b_h[2*nb][0] = r0; b_h[2*nb][1] = r1;
                b_h[2*nb+1][0] = r2; b_h[2*nb+1][1] = r3;
                ldsm4(bd + 9216, r0, r1, r2, r3);
                b_l[2*nb][0] = r0; b_l[2*nb][1] = r1;
                b_l[2*nb+1][0] = r2; b_l[2*nb+1][1] = r3;
            }
#pragma unroll
            for (int ni = 0; ni < 4; ni++) mma_bf16(acc[ni], a_h, b_h[ni]);
#pragma unroll
            for (int ni = 0; ni < 4; ni++) mma_bf16(acc[ni], a_h, b_l[ni]);
#pragma unroll
            for (int ni = 0; ni < 4; ni++) mma_bf16(acc[ni], a_l, b_h[ni]);
        }
#pragma unroll
        for (int half = 0; half < 2; half++) {
            int i = c*64 + mB + (lane >> 2) + half * 8;
#pragma unroll
            for (int ni = 0; ni < 4; ni++) {
                int p = nB + ni*8 + 2*(lane & 3);
                float* dst = &g_y[(size_t)i*DIN + h*HD + p];
                dst[0] = acc[ni][half*2];
                dst[1] = acc[ni][half*2+1];
            }
        }
    }

    {   // states
        const int mB = (w & 3) * 16, nB = (w >> 2) * 64;
        float acc[8][4] = {};
#pragma unroll
        for (int ks = 0; ks < 4; ks++) {
            uint32_t a_h[4], a_l[4], b_h[8][2], b_l[8][2];
            uint32_t ad = aX + (mB + (lane & 15)) * 144 + ((lane >> 4) << 4) + ks * 32;
            ldsm4(ad, a_h[0], a_h[1], a_h[2], a_h[3]);
            ldsm4(ad + 9216, a_l[0], a_l[1], a_l[2], a_l[3]);
#pragma unroll
            for (int nb = 0; nb < 4; nb++) {
                uint32_t bd = aB + (nB + nb*16 + ((lane >> 4) << 3) + (lane & 7)) * 144
                            + (((lane >> 3) & 1) << 4) + ks * 32;
                uint32_t r0, r1, r2, r3;
                ldsm4(bd, r0, r1, r2, r3);
                b_h[2*nb][0] = r0; b_h[2*nb][1] = r1;
                b_h[2*nb+1][0] = r2; b_h[2*nb+1][1] = r3;
                ldsm4(bd + 18432, r0, r1, r2, r3);
                b_l[2*nb][0] = r0; b_l[2*nb][1] = r1;
                b_l[2*nb+1][0] = r2; b_l[2*nb+1][1] = r3;
            }
#pragma unroll
            for (int ni = 0; ni < 8; ni++) mma_bf16(acc[ni], a_h, b_h[ni]);
#pragma unroll
            for (int ni = 0; ni < 8; ni++) mma_bf16(acc[ni], a_h, b_l[ni]);
#pragma unroll
            for (int ni = 0; ni < 8; ni++) mma_bf16(acc[ni], a_l, b_h[ni]);
        }
#pragma unroll
        for (int half = 0; half < 2; half++) {
            int p = mB + (lane >> 2) + half * 8;
#pragma unroll
            for (int ni = 0; ni < 8; ni++) {
                int n = nB + ni*8 + 2*(lane & 3);
                float* dst = &g_states[(size_t)((c*NH + h)*HD + p)*DSTATE + n];
                dst[0] = acc[ni][half*2];
                dst[1] = acc[ni][half*2+1];
            }
        }
    }
}

__global__ void scan_kernel() {
    int idx = blockIdx.x*256 + threadIdx.x;
    int h = idx / (HD*DSTATE);
    int rem = idx % (HD*DSTATE);
    float S = 0.f;
    for (int c = 0; c < NCH; c++) {
        size_t off = (size_t)(c*NH + h)*HD*DSTATE + rem;
        float cur = g_states[off];
        g_states[off] = S;
        S = g_Aexp[c*NH + h]*S + cur;
    }
}

// ============ TENSOR-CORE yoff ============
#define YF_CH  0
#define YF_CL  17408
#define YF_SH  34816
#define YF_SL  52224
#define YF_A   69632
#define YOFF_SMEM 69888

__global__ void __launch_bounds__(256)
yoff_kernel(const float* __restrict__ Dp) {
    extern __shared__ char dsm[];
    __nv_bfloat16* sCh = (__nv_bfloat16*)(dsm + YF_CH);
    __nv_bfloat16* sCl = (__nv_bfloat16*)(dsm + YF_CL);
    __nv_bfloat16* sSh = (__nv_bfloat16*)(dsm + YF_SH);
    __nv_bfloat16* sSl = (__nv_bfloat16*)(dsm + YF_SL);
    float* sA = (float*)(dsm + YF_A);
    const uint32_t sbase = smem_u32(dsm);

    const int c = blockIdx.x, h = blockIdx.y, tid = threadIdx.x;
    const int w = tid >> 5, lane = tid & 31;

    for (int idx = tid; idx < 64*128; idx += 256) {
        int r = idx >> 7, n = idx & 127;
        float cv = g_xBC[(size_t)(c*64 + r)*CONVD + DIN + DSTATE + n];
        split_bf16(cv, sCh[r*136 + n], sCl[r*136 + n]);
        float sv = g_states[(size_t)((c*NH + h)*HD + r)*DSTATE + n];
        split_bf16(sv, sSh[r*136 + n], sSl[r*136 + n]);
    }
    if (tid < 64) sA[tid] = __expf(g_acs[(c*64 + tid)*NH + h]);
    __syncthreads();

    const uint32_t aC = sbase + YF_CH, aS = sbase + YF_SH;
    const int mB = (w & 3) * 16, nB = (w >> 2) * 32;
    float acc[4][4] = {};
#pragma unroll
    for (int ks = 0; ks < 8; ks++) {
        uint32_t a_h[4], a_l[4], b_h[4][2], b_l[4][2];
        uint32_t ad = aC + (mB + (lane & 15)) * 272 + ((lane >> 4) << 4) + ks * 32;
        ldsm4(ad, a_h[0], a_h[1], a_h[2], a_h[3]);
        ldsm4(ad + 17408, a_l[0], a_l[1], a_l[2], a_l[3]);
#pragma unroll
        for (int nb = 0; nb < 2; nb++) {
            uint32_t bd = aS + (nB + nb*16 + ((lane >> 4) << 3) + (lane & 7)) * 272
                        + (((lane >> 3) & 1) << 4) + ks * 32;
            uint32_t r0, r1, r2, r3;
            ldsm4(bd, r0, r1, r2, r3);
            b_h[2*nb][0] = r0; b_h[2*nb][1] = r1;
            b_h[2*nb+1][0] = r2; b_h[2*nb+1][1] = r3;
            ldsm4(bd + 17408, r0, r1, r2, r3);
            b_l[2*nb][0] = r0; b_l[2*nb][1] = r1;
            b_l[2*nb+1][0] = r2; b_l[2*nb+1][1] = r3;
        }
#pragma unroll
        for (int ni = 0; ni < 4; ni++) mma_bf16(acc[ni], a_h, b_h[ni]);
#pragma unroll
        for (int ni = 0; ni < 4; ni++) mma_bf16(acc[ni], a_h, b_l[ni]);
#pragma unroll
        for (int ni = 0; ni < 4; ni++) mma_bf16(acc[ni], a_l, b_h[ni]);
    }
    float dsk = Dp[h];
#pragma unroll
    for (int half = 0; half < 2; half++) {
        int il = mB + (lane >> 2) + half * 8;
        int l = c*64 + il;
        float dec = sA[il];
#pragma unroll
        for (int ni = 0; ni < 4; ni++) {
            int p = nB + ni*8 + 2*(lane & 3);
            float* yp = &g_y[(size_t)l*DIN + h*HD + p];
            const float* xb = &g_xBC[(size_t)l*CONVD + h*HD + p];
            yp[0] += acc[ni][half*2]   * dec + xb[0]*dsk;
            yp[1] += acc[ni][half*2+1] * dec + xb[1]*dsk;
        }
    }
}

// ---------------- launch ----------------
extern "C" void kernel_launch(void* const* d_in, const int* in_sizes, int n_in,
                              void* d_out, int out_size) {
    const int*   ids  = (const int*)  d_in[0];
    const float* emb  = (const float*)d_in[1];
    const float* inw  = (const float*)d_in[2];
    const float* cw   = (const float*)d_in[3];
    const float* cb   = (const float*)d_in[4];
    const float* dtb  = (const float*)d_in[5];
    const float* alog = (const float*)d_in[6];
    const float* Dp   = (const float*)d_in[7];
    const float* mnw  = (const float*)d_in[8];
    const float* ow   = (const float*)d_in[9];
    const float* lnw  = (const float*)d_in[10];
    const float* nfw  = (const float*)d_in[11];
    float* out = (float*)d_out;

    float *px, *pzx;
    __nv_bfloat16 *pinwh, *pinwl, *puh, *pul;
    __half *powh16, *powl16, *pyn16, *pembh, *pu16;
    cudaGetSymbolAddress((void**)&px,    g_x);
    cudaGetSymbolAddress((void**)&pzx,   g_zx);
    cudaGetSymbolAddress((void**)&pinwh, g_inwh);
    cudaGetSymbolAddress((void**)&pinwl, g_inwl);
    cudaGetSymbolAddress((void**)&puh,   g_uh);
    cudaGetSymbolAddress((void**)&pul,   g_ul);
    cudaGetSymbolAddress((void**)&powh16, g_owh16);
    cudaGetSymbolAddress((void**)&powl16, g_owl16);
    cudaGetSymbolAddress((void**)&pyn16, g_yn16);
    cudaGetSymbolAddress((void**)&pembh, g_embh);
    cudaGetSymbolAddress((void**)&pu16,  g_u16);

    cudaFuncSetAttribute(gemm_tc,      cudaFuncAttributeMaxDynamicSharedMemorySize, GEMM_SMEM);
    cudaFuncSetAttribute(gemm_half,    cudaFuncAttributeMaxDynamicSharedMemorySize, GEMMH_SMEM);
    cudaFuncSetAttribute(gemm_half2,   cudaFuncAttributeMaxDynamicSharedMemorySize, GEMM2_SMEM);
    cudaFuncSetAttribute(cb_kernel,    cudaFuncAttributeMaxDynamicSharedMemorySize, CB_SMEM);
    cudaFuncSetAttribute(chunk_kernel, cudaFuncAttributeMaxDynamicSharedMemorySize, CHUNK_SMEM);
    cudaFuncSetAttribute(yoff_kernel,  cudaFuncAttributeMaxDynamicSharedMemorySize, YOFF_SMEM);

    // weight prep
    convert_half_kernel<<<(NV*DM/4 + 255)/256, 256>>>(emb, pembh, NV*DM/4);
    split_kernel<<<(NL*DPROJ*DM/4 + 255)/256, 256>>>(inw, pinwh, pinwl, NL*DPROJ*DM/4);
    split_half_kernel<<<(NL*DM*DIN + 255)/256, 256>>>(ow, powh16, powl16, NL*DM*DIN);

    embed_kernel<<<SEQ, 256>>>(ids, emb);

    for (int i = 0; i < NL; i++) {
        rmsnorm_split_kernel<<<SEQ, 256>>>(px, lnw + (size_t)i*DM, puh, pul);
        gemm_tc<<<dim3(SEQ/128, (DPROJ + 127)/128), 256, GEMM_SMEM>>>(
            puh, pul, pinwh + (size_t)i*DPROJ*DM, pinwl + (size_t)i*DPROJ*DM,
            pzx, SEQ, DPROJ, DM);
        conv_dtacs_kernel<<<CONV_BLKS + 96, 256>>>(
            cw + (size_t)i*CONVD*4, cb + (size_t)i*CONVD, dtb + i*NH, alog + i*NH);
        cb_kernel<<<NCH, 256, CB_SMEM>>>();
        chunk_kernel<<<dim3(NCH, NH), 256, CHUNK_SMEM>>>();
        scan_kernel<<<NH*HD*DSTATE/256, 256>>>();
        yoff_kernel<<<dim3(NCH, NH), 256, YOFF_SMEM>>>(Dp + i*NH);
        gated_rmsnorm_kernel<<<SEQ, 256>>>(mnw + (size_t)i*DIN);
        gemm_half2<<<dim3(SEQ/128, DM/128), 256, GEMM2_SMEM>>>(
            pyn16, powh16 + (size_t)i*DM*DIN, powl16 + (size_t)i*DM*DIN,
            px, px, SEQ, DM, DIN);
    }

    rmsnorm_half_kernel<<<SEQ, 256>>>(px, nfw, pu16);
    gemm_half<<<dim3(SEQ/128, (NV + 127)/128), 256, GEMMH_SMEM>>>(
        pu16, pembh, out, SEQ, NV, DM);
}

// round 16
// speedup vs baseline: 1.0110x; 1.0110x over previous
#include <cuda_runtime.h>
#include <cuda_bf16.h>
#include <cuda_fp16.h>
#include <math.h>
#include <stdint.h>

#define SEQ    2048
#define DM     768
#define NL     4
#define DSTATE 128
#define HD     64
#define NCH    32
#define DIN    1536
#define NH     24
#define CONVD  1792
#define DPROJ  3352
#define NV     50288

// ---------------- scratch (device globals) ----------------
__device__ __align__(128) float g_x[SEQ*DM];
__device__ __align__(128) float g_zx[SEQ*DPROJ];
__device__ __align__(128) float g_xBC[SEQ*CONVD];
__device__ __align__(128) float g_dt[SEQ*NH];
__device__ __align__(128) float g_acs[SEQ*NH];
__device__ __align__(128) float g_Aexp[NCH*NH];
__device__ __align__(128) float g_cb[NCH*64*64];       // [c][i][j] = CB[i][j]
__device__ __align__(128) float g_states[NCH*NH*HD*DSTATE];
__device__ __align__(128) float g_y[SEQ*DIN];

// bf16 split operands (in_proj, 3-term)
__device__ __align__(128) __nv_bfloat16 g_inwh[NL*DPROJ*DM];
__device__ __align__(128) __nv_bfloat16 g_inwl[NL*DPROJ*DM];
__device__ __align__(128) __nv_bfloat16 g_uh[SEQ*DM];
__device__ __align__(128) __nv_bfloat16 g_ul[SEQ*DM];

// fp16 operands (out_proj 2-term, logits 1-term)
__device__ __align__(128) __half g_owh16[NL*DM*DIN];
__device__ __align__(128) __half g_owl16[NL*DM*DIN];
__device__ __align__(128) __half g_yn16[SEQ*DIN];
__device__ __align__(128) __half g_embh[NV*DM];
__device__ __align__(128) __half g_u16[SEQ*DM];

// ---------------- PTX helpers ----------------
__device__ __forceinline__ uint32_t smem_u32(const void* p) {
    uint32_t a;
    asm("{ .reg .u64 t; cvta.to.shared.u64 t, %1; cvt.u32.u64 %0, t; }" : "=r"(a) : "l"(p));
    return a;
}
__device__ __forceinline__ void cpa16(uint32_t dst, const void* src) {
    asm volatile("cp.async.cg.shared.global [%0], [%1], 16;" :: "r"(dst), "l"(src) : "memory");
}
#define CP_COMMIT() asm volatile("cp.async.commit_group;" ::: "memory")
#define CP_WAIT(n)  asm volatile("cp.async.wait_group %0;" :: "n"(n) : "memory")

__device__ __forceinline__ void ldsm4(uint32_t addr, uint32_t& r0, uint32_t& r1,
                                      uint32_t& r2, uint32_t& r3) {
    asm volatile("ldmatrix.sync.aligned.m8n8.x4.shared.b16 {%0,%1,%2,%3}, [%4];"
                 : "=r"(r0), "=r"(r1), "=r"(r2), "=r"(r3) : "r"(addr));
}
__device__ __forceinline__ void mma_bf16(float* d, const uint32_t* a, const uint32_t* b) {
    asm volatile(
        "mma.sync.aligned.m16n8k16.row.col.f32.bf16.bf16.f32 "
        "{%0,%1,%2,%3}, {%4,%5,%6,%7}, {%8,%9}, {%0,%1,%2,%3};"
        : "+f"(d[0]), "+f"(d[1]), "+f"(d[2]), "+f"(d[3])
        : "r"(a[0]), "r"(a[1]), "r"(a[2]), "r"(a[3]), "r"(b[0]), "r"(b[1]));
}
__device__ __forceinline__ void mma_f16(float* d, const uint32_t* a, const uint32_t* b) {
    asm volatile(
        "mma.sync.aligned.m16n8k16.row.col.f32.f16.f16.f32 "
        "{%0,%1,%2,%3}, {%4,%5,%6,%7}, {%8,%9}, {%0,%1,%2,%3};"
        : "+f"(d[0]), "+f"(d[1]), "+f"(d[2]), "+f"(d[3])
        : "r"(a[0]), "r"(a[1]), "r"(a[2]), "r"(a[3]), "r"(b[0]), "r"(b[1]));
}
__device__ __forceinline__ void split_bf16(float v, __nv_bfloat16& h, __nv_bfloat16& l) {
    h = __float2bfloat16(v);
    l = __float2bfloat16(v - __bfloat162float(h));
}

#define RS 80
#define A_BYTES (128*RS)              // 10240

// ================= split-bf16 3-term GEMM, 128x128, 2-stage (in_proj) ========
#define SLABB     (4*A_BYTES)         // 40960
#define GEMM_SMEM (2*SLABB)           // 81920

__global__ void __launch_bounds__(256, 1)
gemm_tc(const __nv_bfloat16* __restrict__ Ah, const __nv_bfloat16* __restrict__ Al,
        const __nv_bfloat16* __restrict__ Bh, const __nv_bfloat16* __restrict__ Bl,
        float* __restrict__ C, int M, int N, int K) {
    extern __shared__ char dsm[];
    const uint32_t sbase = smem_u32(dsm);
    const int tid = threadIdx.x, wid = tid >> 5, lane = tid & 31;
    const int m0 = blockIdx.x * 128, n0 = blockIdx.y * 128;
    const int nslab = K >> 5;
    const int mw = (wid & 1) * 64, nw = (wid >> 1) * 32;

    float acc[4][4][4];
#pragma unroll
    for (int i = 0; i < 4; i++)
#pragma unroll
        for (int j = 0; j < 4; j++)
#pragma unroll
            for (int k = 0; k < 4; k++) acc[i][j][k] = 0.f;

    auto load_slab = [&](int s, int b) {
        const int k0 = s << 5;
        const uint32_t base = sbase + b * SLABB;
#pragma unroll
        for (int t = 0; t < 2; t++) {
            int idx = tid + t * 256;
            int r = idx >> 2, c = idx & 3;
            uint32_t d = base + r * RS + c * 16;
            size_t g = (size_t)(m0 + r) * K + k0 + c * 8;
            cpa16(d, Ah + g);
            cpa16(d + A_BYTES, Al + g);
        }
#pragma unroll
        for (int t = 0; t < 2; t++) {
            int idx = tid + t * 256;
            int r = idx >> 2, c = idx & 3;
            int rn = n0 + r; if (rn > N - 1) rn = N - 1;
            uint32_t d = base + 2 * A_BYTES + r * RS + c * 16;
            size_t g = (size_t)rn * K + k0 + c * 8;
            cpa16(d, Bh + g);
            cpa16(d + A_BYTES, Bl + g);
        }
    };

    load_slab(0, 0);
    CP_COMMIT();

    for (int s = 0; s < nslab; s++) {
        const int b = s & 1;
        if (s + 1 < nslab) {
            load_slab(s + 1, b ^ 1);
            CP_COMMIT();
            CP_WAIT(1);
        } else {
            CP_WAIT(0);
        }
        __syncthreads();

        const uint32_t abase = sbase + b * SLABB;
        const uint32_t bbase = abase + 2 * A_BYTES;
#pragma unroll
        for (int ks = 0; ks < 2; ks++) {
            uint32_t a_h[4][4], a_l[4][4], b_h[4][2], b_l[4][2];
#pragma unroll
            for (int mi = 0; mi < 4; mi++) {
                uint32_t ad = abase + (mw + mi * 16 + (lane & 15)) * RS
                            + ((lane >> 4) << 4) + ks * 32;
                ldsm4(ad, a_h[mi][0], a_h[mi][1], a_h[mi][2], a_h[mi][3]);
                ldsm4(ad + A_BYTES, a_l[mi][0], a_l[mi][1], a_l[mi][2], a_l[mi][3]);
            }
#pragma unroll
            for (int nb = 0; nb < 2; nb++) {
                uint32_t bd = bbase + (nw + nb * 16 + ((lane >> 4) << 3) + (lane & 7)) * RS
                            + (((lane >> 3) & 1) << 4) + ks * 32;
                uint32_t r0, r1, r2, r3;
                ldsm4(bd, r0, r1, r2, r3);
                b_h[2*nb][0] = r0; b_h[2*nb][1] = r1;
                b_h[2*nb+1][0] = r2; b_h[2*nb+1][1] = r3;
                ldsm4(bd + A_BYTES, r0, r1, r2, r3);
                b_l[2*nb][0] = r0; b_l[2*nb][1] = r1;
                b_l[2*nb+1][0] = r2; b_l[2*nb+1][1] = r3;
            }
#pragma unroll
            for (int mi = 0; mi < 4; mi++)
#pragma unroll
                for (int ni = 0; ni < 4; ni++)
                    mma_bf16(acc[mi][ni], a_h[mi], b_h[ni]);
#pragma unroll
            for (int mi = 0; mi < 4; mi++)
#pragma unroll
                for (int ni = 0; ni < 4; ni++)
                    mma_bf16(acc[mi][ni], a_h[mi], b_l[ni]);
#pragma unroll
            for (int mi = 0; mi < 4; mi++)
#pragma unroll
                for (int ni = 0; ni < 4; ni++)
                    mma_bf16(acc[mi][ni], a_l[mi], b_h[ni]);
        }
        __syncthreads();
    }

#pragma unroll
    for (int mi = 0; mi < 4; mi++) {
#pragma unroll
        for (int half = 0; half < 2; half++) {
            int m = m0 + mw + mi * 16 + (lane >> 2) + half * 8;
#pragma unroll
            for (int ni = 0; ni < 4; ni++) {
                int n = n0 + nw + ni * 8 + 2 * (lane & 3);
                if (n < N) {
                    float* p = C + (size_t)m * N + n;
                    p[0] = acc[mi][ni][half*2];
                    p[1] = acc[mi][ni][half*2+1];
                }
            }
        }
    }
}

// ================= fp16 1-term GEMM, 128x128, 2-stage (logits) ===============
#define SLABH      (2*A_BYTES)        // 20480
#define GEMMH_SMEM (2*SLABH)          // 40960

__global__ void __launch_bounds__(256, 2)
gemm_half(const __half* __restrict__ A, const __half* __restrict__ B,
          float* __restrict__ C, int M, int N, int K) {
    extern __shared__ char dsm[];
    const uint32_t sbase = smem_u32(dsm);
    const int tid = threadIdx.x, wid = tid >> 5, lane = tid & 31;
    const int m0 = blockIdx.x * 128, n0 = blockIdx.y * 128;
    const int nslab = K >> 5;
    const int mw = (wid & 1) * 64, nw = (wid >> 1) * 32;

    float acc[4][4][4];
#pragma unroll
    for (int i = 0; i < 4; i++)
#pragma unroll
        for (int j = 0; j < 4; j++)
#pragma unroll
            for (int k = 0; k < 4; k++) acc[i][j][k] = 0.f;

    auto load_slab = [&](int s, int b) {
        const int k0 = s << 5;
        const uint32_t base = sbase + b * SLABH;
#pragma unroll
        for (int t = 0; t < 2; t++) {
            int idx = tid + t * 256;
            int r = idx >> 2, c = idx & 3;
            uint32_t d = base + r * RS + c * 16;
            cpa16(d, A + (size_t)(m0 + r) * K + k0 + c * 8);
            int rn = n0 + r; if (rn > N - 1) rn = N - 1;
            cpa16(d + A_BYTES, B + (size_t)rn * K + k0 + c * 8);
        }
    };

    load_slab(0, 0);
    CP_COMMIT();

    for (int s = 0; s < nslab; s++) {
        const int b = s & 1;
        if (s + 1 < nslab) {
            load_slab(s + 1, b ^ 1);
            CP_COMMIT();
            CP_WAIT(1);
        } else {
            CP_WAIT(0);
        }
        __syncthreads();

        const uint32_t abase = sbase + b * SLABH;
        const uint32_t bbase = abase + A_BYTES;
#pragma unroll
        for (int ks = 0; ks < 2; ks++) {
            uint32_t a_f[4][4], b_f[4][2];
#pragma unroll
            for (int mi = 0; mi < 4; mi++) {
                uint32_t ad = abase + (mw + mi * 16 + (lane & 15)) * RS
                            + ((lane >> 4) << 4) + ks * 32;
                ldsm4(ad, a_f[mi][0], a_f[mi][1], a_f[mi][2], a_f[mi][3]);
            }
#pragma unroll
            for (int nb = 0; nb < 2; nb++) {
                uint32_t bd = bbase + (nw + nb * 16 + ((lane >> 4) << 3) + (lane & 7)) * RS
                            + (((lane >> 3) & 1) << 4) + ks * 32;
                uint32_t r0, r1, r2, r3;
                ldsm4(bd, r0, r1, r2, r3);
                b_f[2*nb][0] = r0; b_f[2*nb][1] = r1;
                b_f[2*nb+1][0] = r2; b_f[2*nb+1][1] = r3;
            }
#pragma unroll
            for (int mi = 0; mi < 4; mi++)
#pragma unroll
                for (int ni = 0; ni < 4; ni++)
                    mma_f16(acc[mi][ni], a_f[mi], b_f[ni]);
        }
        __syncthreads();
    }

#pragma unroll
    for (int mi = 0; mi < 4; mi++) {
#pragma unroll
        for (int half = 0; half < 2; half++) {
            int m = m0 + mw + mi * 16 + (lane >> 2) + half * 8;
#pragma unroll
            for (int ni = 0; ni < 4; ni++) {
                int n = n0 + nw + ni * 8 + 2 * (lane & 3);
                if (n < N) {
                    float* p = C + (size_t)m * N + n;
                    p[0] = acc[mi][ni][half*2];
                    p[1] = acc[mi][ni][half*2+1];
                }
            }
        }
    }
}

// ================= fp16 2-term GEMM, 128x128, 2-stage (out_proj) =============
#define SLAB2      (3*A_BYTES)        // 30720
#define GEMM2_SMEM (2*SLAB2)          // 61440

__global__ void __launch_bounds__(256, 2)
gemm_half2(const __half* __restrict__ A, const __half* __restrict__ Bh,
           const __half* __restrict__ Bl, const float* __restrict__ addsrc,
           float* __restrict__ C, int M, int N, int K) {
    extern __shared__ char dsm[];
    const uint32_t sbase = smem_u32(dsm);
    const int tid = threadIdx.x, wid = tid >> 5, lane = tid & 31;
    const int m0 = blockIdx.x * 128, n0 = blockIdx.y * 128;
    const int nslab = K >> 5;
    const int mw = (wid & 1) * 64, nw = (wid >> 1) * 32;

    float acc[4][4][4];
#pragma unroll
    for (int i = 0; i < 4; i++)
#pragma unroll
        for (int j = 0; j < 4; j++)
#pragma unroll
            for (int k = 0; k < 4; k++) acc[i][j][k] = 0.f;

    auto load_slab = [&](int s, int b) {
        const int k0 = s << 5;
        const uint32_t base = sbase + b * SLAB2;
#pragma unroll
        for (int t = 0; t < 2; t++) {
            int idx = tid + t * 256;
            int r = idx >> 2, c = idx & 3;
            uint32_t d = base + r * RS + c * 16;
            cpa16(d, A + (size_t)(m0 + r) * K + k0 + c * 8);
            int rn = n0 + r; if (rn > N - 1) rn = N - 1;
            size_t g = (size_t)rn * K + k0 + c * 8;
            cpa16(d + A_BYTES, Bh + g);
            cpa16(d + 2 * A_BYTES, Bl + g);
        }
    };

    load_slab(0, 0);
    CP_COMMIT();

    for (int s = 0; s < nslab; s++) {
        const int b = s & 1;
        if (s + 1 < nslab) {
            load_slab(s + 1, b ^ 1);
            CP_COMMIT();
            CP_WAIT(1);
        } else {
            CP_WAIT(0);
        }
        __syncthreads();

        const uint32_t abase = sbase + b * SLAB2;
        const uint32_t bbase = abase + A_BYTES;
#pragma unroll
        for (int ks = 0; ks < 2; ks++) {
            uint32_t a_f[4][4], b_h[4][2], b_l[4][2];
#pragma unroll
            for (int mi = 0; mi < 4; mi++) {
                uint32_t ad = abase + (mw + mi * 16 + (lane & 15)) * RS
                            + ((lane >> 4) << 4) + ks * 32;
                ldsm4(ad, a_f[mi][0], a_f[mi][1], a_f[mi][2], a_f[mi][3]);
            }
#pragma unroll
            for (int nb = 0; nb < 2; nb++) {
                uint32_t bd = bbase + (nw + nb * 16 + ((lane >> 4) << 3) + (lane & 7)) * RS
                            + (((lane >> 3) & 1) << 4) + ks * 32;
                uint32_t r0, r1, r2, r3;
                ldsm4(bd, r0, r1, r2, r3);
                b_h[2*nb][0] = r0; b_h[2*nb][1] = r1;
                b_h[2*nb+1][0] = r2; b_h[2*nb+1][1] = r3;
                ldsm4(bd + A_BYTES, r0, r1, r2, r3);
                b_l[2*nb][0] = r0; b_l[2*nb][1] = r1;
                b_l[2*nb+1][0] = r2; b_l[2*nb+1][1] = r3;
            }
#pragma unroll
            for (int mi = 0; mi < 4; mi++)
#pragma unroll
                for (int ni = 0; ni < 4; ni++)
                    mma_f16(acc[mi][ni], a_f[mi], b_h[ni]);
#pragma unroll
            for (int mi = 0; mi < 4; mi++)
#pragma unroll
                for (int ni = 0; ni < 4; ni++)
                    mma_f16(acc[mi][ni], a_f[mi], b_l[ni]);
        }
        __syncthreads();
    }

#pragma unroll
    for (int mi = 0; mi < 4; mi++) {
#pragma unroll
        for (int half = 0; half < 2; half++) {
            int m = m0 + mw + mi * 16 + (lane >> 2) + half * 8;
#pragma unroll
            for (int ni = 0; ni < 4; ni++) {
                int n = n0 + nw + ni * 8 + 2 * (lane & 3);
                if (n < N) {
                    float2 v = make_float2(acc[mi][ni][half*2], acc[mi][ni][half*2+1]);
                    const float* q = addsrc + (size_t)m * N + n;
                    v.x += q[0]; v.y += q[1];
                    float* p = C + (size_t)m * N + n;
                    p[0] = v.x; p[1] = v.y;
                }
            }
        }
    }
}

// ---------------- misc kernels ----------------
__device__ __forceinline__ float block_sum(float v) {
    __shared__ float red[256];
    int t = threadIdx.x;
    red[t] = v; __syncthreads();
    for (int s = 128; s > 0; s >>= 1) {
        if (t < s) red[t] += red[t + s];
        __syncthreads();
    }
    float r = red[0];
    __syncthreads();
    return r;
}

__global__ void embed_kernel(const int* __restrict__ ids, const float* __restrict__ emb) {
    int l = blockIdx.x;
    int id = ids[l];
    const float4* src = (const float4*)(emb + (size_t)id*DM);
    float4* dst = (float4*)(g_x + (size_t)l*DM);
    for (int d = threadIdx.x; d < DM/4; d += 256)
        dst[d] = src[d];
}

__global__ void split_kernel(const float* __restrict__ s, __nv_bfloat16* __restrict__ h,
                             __nv_bfloat16* __restrict__ l, int n4) {
    int i = blockIdx.x*256 + threadIdx.x;
    if (i >= n4) return;
    float4 v = ((const float4*)s)[i];
    __nv_bfloat16 h0 = __float2bfloat16(v.x), h1 = __float2bfloat16(v.y);
    __nv_bfloat16 h2 = __float2bfloat16(v.z), h3 = __float2bfloat16(v.w);
    h[i*4+0] = h0; h[i*4+1] = h1; h[i*4+2] = h2; h[i*4+3] = h3;
    l[i*4+0] = __float2bfloat16(v.x - __bfloat162float(h0));
    l[i*4+1] = __float2bfloat16(v.y - __bfloat162float(h1));
    l[i*4+2] = __float2bfloat16(v.z - __bfloat162float(h2));
    l[i*4+3] = __float2bfloat16(v.w - __bfloat162float(h3));
}

__global__ void split_half_kernel(const float* __restrict__ s, __half* __restrict__ h,
                                  __half* __restrict__ l, int n) {
    int i = blockIdx.x*256 + threadIdx.x;
    if (i >= n) return;
    float v = s[i];
    __half hv = __float2half(v);
    h[i] = hv;
    l[i] = __float2half(v - __half2float(hv));
}

__global__ void convert_half_kernel(const float* __restrict__ s, __half* __restrict__ d, int n4) {
    int i = blockIdx.x*256 + threadIdx.x;
    if (i >= n4) return;
    float4 v = ((const float4*)s)[i];
    ((__half2*)d)[i*2]   = __floats2half2_rn(v.x, v.y);
    ((__half2*)d)[i*2+1] = __floats2half2_rn(v.z, v.w);
}

__global__ void rmsnorm_split_kernel(const float* __restrict__ in, const float* __restrict__ w,
                                     __nv_bfloat16* __restrict__ oh, __nv_bfloat16* __restrict__ ol) {
    int row = blockIdx.x;
    const float* x = in + (size_t)row*DM;
    float s = 0.f;
    for (int i = threadIdx.x; i < DM; i += 256) { float v = x[i]; s += v*v; }
    float tot = block_sum(s);
    float sc = rsqrtf(tot / (float)DM + 1e-5f);
    for (int i = threadIdx.x; i < DM; i += 256) {
        float v = x[i] * sc * w[i];
        __nv_bfloat16 h = __float2bfloat16(v);
        oh[(size_t)row*DM + i] = h;
        ol[(size_t)row*DM + i] = __float2bfloat16(v - __bfloat162float(h));
    }
}

__global__ void rmsnorm_half_kernel(const float* __restrict__ in, const float* __restrict__ w,
                                    __half* __restrict__ out) {
    int row = blockIdx.x;
    const float* x = in + (size_t)row*DM;
    float s = 0.f;
    for (int i = threadIdx.x; i < DM; i += 256) { float v = x[i]; s += v*v; }
    float tot = block_sum(s);
    float sc = rsqrtf(tot / (float)DM + 1e-5f);
    for (int i = threadIdx.x; i < DM; i += 256)
        out[(size_t)row*DM + i] = __float2half(x[i] * sc * w[i]);
}

__global__ void gated_rmsnorm_kernel(const float* __restrict__ w) {
    int row = blockIdx.x;
    __shared__ float tbuf[DIN];
    float s = 0.f;
    for (int i = threadIdx.x; i < DIN; i += 256) {
        float v = g_y[(size_t)row*DIN + i];
        float z = g_zx[(size_t)row*DPROJ + i];
        float g = v * (z / (1.f + __expf(-z)));
        tbuf[i] = g; s += g*g;
    }
    float tot = block_sum(s);
    float sc = rsqrtf(tot / (float)DIN + 1e-5f);
    for (int i = threadIdx.x; i < DIN; i += 256)
        g_yn16[(size_t)row*DIN + i] = __float2half(tbuf[i] * sc * w[i]);
}

// conv (blocks 0..3583) fused with dtacs (blocks 3584..3679); both depend only on g_zx
#define CONV_BLKS (SEQ*(CONVD/4)/256)   // 3584
__global__ void __launch_bounds__(256)
conv_dtacs_kernel(const float* __restrict__ cw, const float* __restrict__ cb,
                  const float* __restrict__ dtb, const float* __restrict__ alog) {
    if (blockIdx.x < CONV_BLKS) {
        int idx = blockIdx.x*256 + threadIdx.x;
        const int C4 = CONVD/4;
        int l = idx / C4, ch4 = (idx % C4) * 4;

        float4 bias = *(const float4*)(cb + ch4);
        float s0 = bias.x, s1 = bias.y, s2 = bias.z, s3 = bias.w;
        float4 w0 = *(const float4*)(cw + ch4*4);
        float4 w1 = *(const float4*)(cw + ch4*4 + 4);
        float4 w2 = *(const float4*)(cw + ch4*4 + 8);
        float4 w3 = *(const float4*)(cw + ch4*4 + 12);
        const float wa[4][4] = {{w0.x,w0.y,w0.z,w0.w},{w1.x,w1.y,w1.z,w1.w},
                                {w2.x,w2.y,w2.z,w2.w},{w3.x,w3.y,w3.z,w3.w}};
#pragma unroll
        for (int k = 0; k < 4; k++) {
            int t = l - 3 + k;
            if (t >= 0) {
                float4 xz = *(const float4*)(g_zx + (size_t)t*DPROJ + DIN + ch4);
                s0 += wa[0][k]*xz.x; s1 += wa[1][k]*xz.y;
                s2 += wa[2][k]*xz.z; s3 += wa[3][k]*xz.w;
            }
        }
        float4 o;
        o.x = s0 / (1.f + __expf(-s0));
        o.y = s1 / (1.f + __expf(-s1));
        o.z = s2 / (1.f + __expf(-s2));
        o.w = s3 / (1.f + __expf(-s3));
        *(float4*)(g_xBC + (size_t)l*CONVD + ch4) = o;
    } else {
        int b = blockIdx.x - CONV_BLKS;
        int wid = threadIdx.x >> 5, lane = threadIdx.x & 31;
        int h = (b >> 5) * 8 + wid;
        int c = b & 31;
        int l0 = c * 64 + lane * 2;

        float bias = dtb[h];
        float Aneg = -expf(alog[h]);
        float v0 = g_zx[(size_t)l0*DPROJ + DIN + CONVD + h] + bias;
        float v1 = g_zx[(size_t)(l0+1)*DPROJ + DIN + CONVD + h] + bias;
        float dt0 = (v0 > 20.f) ? v0 : log1pf(expf(v0));
        float dt1 = (v1 > 20.f) ? v1 : log1pf(expf(v1));
        g_dt[l0*NH + h] = dt0;
        g_dt[(l0+1)*NH + h] = dt1;
        float a0 = Aneg * dt0, a1 = Aneg * dt1;
        float pair = a0 + a1;
        float s = pair;
#pragma unroll
        for (int o = 1; o < 32; o <<= 1) {
            float t = __shfl_up_sync(0xFFFFFFFFu, s, o);
            if (lane >= o) s += t;
        }
        float excl = s - pair;
        g_acs[l0*NH + h] = excl + a0;
        g_acs[(l0+1)*NH + h] = excl + a0 + a1;
        if (lane == 31) g_Aexp[c*NH + h] = expf(s);
    }
}

// head-shared CB[c][i][j]
#define CB_SMEM (2*64*129*4)
__global__ void __launch_bounds__(256)
cb_kernel() {
    extern __shared__ char dsm[];
    float* sB = (float*)dsm;
    float* sC = sB + 64*129;
    const int c = blockIdx.x, tid = threadIdx.x;

    for (int idx = tid; idx < 64*128; idx += 256) {
        int r = idx >> 7, n = idx & 127;
        const float* row = g_xBC + (size_t)(c*64 + r)*CONVD + DIN;
        sB[r*129 + n] = row[n];
        sC[r*129 + n] = row[DSTATE + n];
    }
    __syncthreads();

    const int i0 = (tid & 15)*4, j0 = (tid >> 4)*4;
    float acc[4][4] = {};
    for (int n = 0; n < 128; n++) {
        float a[4], b[4];
#pragma unroll
        for (int ii = 0; ii < 4; ii++) a[ii] = sC[(i0+ii)*129 + n];
#pragma unroll
        for (int jj = 0; jj < 4; jj++) b[jj] = sB[(j0+jj)*129 + n];
#pragma unroll
        for (int ii = 0; ii < 4; ii++)
#pragma unroll
            for (int jj = 0; jj < 4; jj++) acc[ii][jj] += a[ii]*b[jj];
    }
#pragma unroll
    for (int ii = 0; ii < 4; ii++)
#pragma unroll
        for (int jj = 0; jj < 4; jj++)
            g_cb[c*4096 + (i0+ii)*64 + j0 + jj] = acc[ii][jj];
}

// ============ TENSOR-CORE chunk =========
#define CK_MH   0
#define CK_ML   9216
#define CK_XH   18432
#define CK_XL   27648
#define CK_BH   36864
#define CK_BL   55296
#define CK_ACS  73728
#define CK_DEC  73984
#define CHUNK_SMEM 74240

__global__ void __launch_bounds__(256)
chunk_kernel() {
    extern __shared__ char dsm[];
    __nv_bfloat16* sMh = (__nv_bfloat16*)(dsm + CK_MH);
    __nv_bfloat16* sMl = (__nv_bfloat16*)(dsm + CK_ML);
    __nv_bfloat16* sXh = (__nv_bfloat16*)(dsm + CK_XH);
    __nv_bfloat16* sXl = (__nv_bfloat16*)(dsm + CK_XL);
    __nv_bfloat16* sBh = (__nv_bfloat16*)(dsm + CK_BH);
    __nv_bfloat16* sBl = (__nv_bfloat16*)(dsm + CK_BL);
    float* sAcs = (float*)(dsm + CK_ACS);
    float* sDec = (float*)(dsm + CK_DEC);
    const uint32_t sbase = smem_u32(dsm);

    const int c = blockIdx.x, h = blockIdx.y, tid = threadIdx.x;
    const int w = tid >> 5, lane = tid & 31;

    if (tid < 64) sAcs[tid] = g_acs[(c*64 + tid)*NH + h];
    __syncthreads();
    if (tid < 64) sDec[tid] = __expf(sAcs[63] - sAcs[tid]);
    __syncthreads();

    for (int idx = tid; idx < 64*64; idx += 256) {
        int j = idx >> 6, p = idx & 63;
        float v = g_xBC[(size_t)(c*64 + j)*CONVD + h*HD + p] * g_dt[(c*64 + j)*NH + h];
        split_bf16(v, sXh[p*72 + j], sXl[p*72 + j]);
    }
    for (int idx = tid; idx < 64*64; idx += 256) {
        int i = idx >> 6, j = idx & 63;
        float v = (j <= i) ? g_cb[c*4096 + idx] * __expf(sAcs[i] - sAcs[j]) : 0.f;
        split_bf16(v, sMh[i*72 + j], sMl[i*72 + j]);
    }
    for (int idx = tid; idx < 64*128; idx += 256) {
        int j = idx >> 7, n = idx & 127;
        float v = g_xBC[(size_t)(c*64 + j)*CONVD + DIN + n] * sDec[j];
        split_bf16(v, sBh[n*72 + j], sBl[n*72 + j]);
    }
    __syncthreads();

    const uint32_t aM = sbase + CK_MH, aX = sbase + CK_XH, aB = sbase + CK_BH;

    {   // Y_diag
        const int mB = (w & 3) * 16, nB = (w >> 2) * 32;
        float acc[4][4] = {};
#pragma unroll
        for (int ks = 0; ks < 4; ks++) {
            uint32_t a_h[4], a_l[4], b_h[4][2], b_l[4][2];
            uint32_t ad = aM + (mB + (lane & 15)) * 144 + ((lane >> 4) << 4) + ks * 32;
            ldsm4(ad, a_h[0], a_h[1], a_h[2], a_h[3]);
            ldsm4(ad + 9216, a_l[0], a_l[1], a_l[2], a_l[3]);
#pragma unroll
            for (int nb = 0; nb < 2; nb++) {
                uint32_t bd = aX + (nB + nb*16 + ((lane >> 4) << 3) + (lane & 7)) * 144
                            + (((lane >> 3) & 1) << 4) + ks * 32;
                uint32_t r0, r1, r2, r3;
                ldsm4(bd, r0, r1, r2, r3);
                b_h[2*nb][0] = r0; b_h[2*nb][1] = r1;
                b_h[2*nb+1][0] = r2; b_h[2*nb+1][1] = r3;
                ldsm4(bd + 9216, r0, r1, r2, r3);
                b_l[2*nb][0] = r0; b_l[2*nb][1] = r1;
                b_l[2*nb+1][0] = r2; b_l[2*nb+1][1] = r3;
            }
#pragma unroll
            for (int ni = 0; ni < 4; ni++) mma_bf16(acc[ni], a_h, b_h[ni]);
#pragma unroll
            for (int ni = 0; ni < 4; ni++) mma_bf16(acc[ni], a_h, b_l[ni]);
#pragma unroll
            for (int ni = 0; ni < 4; ni++) mma_bf16(acc[ni], a_l, b_h[ni]);
        }
#pragma unroll
        for (int half = 0; half < 2; half++) {
            int i = c*64 + mB + (lane >> 2) + half * 8;
#pragma unroll
            for (int ni = 0; ni < 4; ni++) {
                int p = nB + ni*8 + 2*(lane & 3);
                float* dst = &g_y[(size_t)i*DIN + h*HD + p];
                dst[0] = acc[ni][half*2];
                dst[1] = acc[ni][half*2+1];
            }
        }
    }

    {   // states
        const int mB = (w & 3) * 16, nB = (w >> 2) * 64;
        float acc[8][4] = {};
#pragma unroll
        for (int ks = 0; ks < 4; ks++) {
            uint32_t a_h[4], a_l[4], b_h[8][2], b_l[8][2];
            uint32_t ad = aX + (mB + (lane & 15)) * 144 + ((lane >> 4) << 4) + ks * 32;
            ldsm4(ad, a_h[0], a_h[1], a_h[2], a_h[3]);
            ldsm4(ad + 9216, a_l[0], a_l[1], a_l[2], a_l[3]);
#pragma unroll
            for (int nb = 0; nb < 4; nb++) {
                uint32_t bd = aB + (nB + nb*16 + ((lane >> 4) << 3) + (lane & 7)) * 144
                            + (((lane >> 3) & 1) << 4) + ks * 32;
                uint32_t r0, r1, r2, r3;
                ldsm4(bd, r0, r1, r2, r3);
                b_h[2*nb][0] = r0; b_h[2*nb][1] = r1;
                b_h[2*nb+1][0] = r2; b_h[2*nb+1][1] = r3;
                ldsm4(bd + 18432, r0, r1, r2, r3);
                b_l[2*nb][0] = r0; b_l[2*nb][1] = r1;
                b_l[2*nb+1][0] = r2; b_l[2*nb+1][1] = r3;
            }
#pragma unroll
            for (int ni = 0; ni < 8; ni++) mma_bf16(acc[ni], a_h, b_h[ni]);
#pragma unroll
            for (int ni = 0; ni < 8; ni++) mma_bf16(acc[ni], a_h, b_l[ni]);
#pragma unroll
            for (int ni = 0; ni < 8; ni++) mma_bf16(acc[ni], a_l, b_h[ni]);
        }
#pragma unroll
        for (int half = 0; half < 2; half++) {
            int p = mB + (lane >> 2) + half * 8;
#pragma unroll
            for (int ni = 0; ni < 8; ni++) {
                int n = nB + ni*8 + 2*(lane & 3);
                float* dst = &g_states[(size_t)((c*NH + h)*HD + p)*DSTATE + n];
                dst[0] = acc[ni][half*2];
                dst[1] = acc[ni][half*2+1];
            }
        }
    }
}

__global__ void scan_kernel() {
    int idx = blockIdx.x*256 + threadIdx.x;
    int h = idx / (HD*DSTATE);
    int rem = idx % (HD*DSTATE);
    float S = 0.f;
    for (int c = 0; c < NCH; c++) {
        size_t off = (size_t)(c*NH + h)*HD*DSTATE + rem;
        float cur = g_states[off];
        g_states[off] = S;
        S = g_Aexp[c*NH + h]*S + cur;
    }
}

// ============ TENSOR-CORE yoff ============
#define YF_CH  0
#define YF_CL  17408
#define YF_SH  34816
#define YF_SL  52224
#define YF_A   69632
#define YOFF_SMEM 69888

__global__ void __launch_bounds__(256)
yoff_kernel(const float* __restrict__ Dp) {
    extern __shared__ char dsm[];
    __nv_bfloat16* sCh = (__nv_bfloat16*)(dsm + YF_CH);
    __nv_bfloat16* sCl = (__nv_bfloat16*)(dsm + YF_CL);
    __nv_bfloat16* sSh = (__nv_bfloat16*)(dsm + YF_SH);
    __nv_bfloat16* sSl = (__nv_bfloat16*)(dsm + YF_SL);
    float* sA = (float*)(dsm + YF_A);
    const uint32_t sbase = smem_u32(dsm);

    const int c = blockIdx.x, h = blockIdx.y, tid = threadIdx.x;
    const int w = tid >> 5, lane = tid & 31;

    for (int idx = tid; idx < 64*128; idx += 256) {
        int r = idx >> 7, n = idx & 127;
        float cv = g_xBC[(size_t)(c*64 + r)*CONVD + DIN + DSTATE + n];
        split_bf16(cv, sCh[r*136 + n], sCl[r*136 + n]);
        float sv = g_states[(size_t)((c*NH + h)*HD + r)*DSTATE + n];
        split_bf16(sv, sSh[r*136 + n], sSl[r*136 + n]);
    }
    if (tid < 64) sA[tid] = __expf(g_acs[(c*64 + tid)*NH + h]);
    __syncthreads();

    const uint32_t aC = sbase + YF_CH, aS = sbase + YF_SH;
    const int mB = (w & 3) * 16, nB = (w >> 2) * 32;
    float acc[4][4] = {};
#pragma unroll
    for (int ks = 0; ks < 8; ks++) {
        uint32_t a_h[4], a_l[4], b_h[4][2], b_l[4][2];
        uint32_t ad = aC + (mB + (lane & 15)) * 272 + ((lane >> 4) << 4) + ks * 32;
        ldsm4(ad, a_h[0], a_h[1], a_h[2], a_h[3]);
        ldsm4(ad + 17408, a_l[0], a_l[1], a_l[2], a_l[3]);
#pragma unroll
        for (int nb = 0; nb < 2; nb++) {
            uint32_t bd = aS + (nB + nb*16 + ((lane >> 4) << 3) + (lane & 7)) * 272
                        + (((lane >> 3) & 1) << 4) + ks * 32;
            uint32_t r0, r1, r2, r3;
            ldsm4(bd, r0, r1, r2, r3);
            b_h[2*nb][0] = r0; b_h[2*nb][1] = r1;
            b_h[2*nb+1][0] = r2; b_h[2*nb+1][1] = r3;
            ldsm4(bd + 17408, r0, r1, r2, r3);
            b_l[2*nb][0] = r0; b_l[2*nb][1] = r1;
            b_l[2*nb+1][0] = r2; b_l[2*nb+1][1] = r3;
        }
#pragma unroll
        for (int ni = 0; ni < 4; ni++) mma_bf16(acc[ni], a_h, b_h[ni]);
#pragma unroll
        for (int ni = 0; ni < 4; ni++) mma_bf16(acc[ni], a_h, b_l[ni]);
#pragma unroll
        for (int ni = 0; ni < 4; ni++) mma_bf16(acc[ni], a_l, b_h[ni]);
    }
    float dsk = Dp[h];
#pragma unroll
    for (int half = 0; half < 2; half++) {
        int il = mB + (lane >> 2) + half * 8;
        int l = c*64 + il;
        float dec = sA[il];
#pragma unroll
        for (int ni = 0; ni < 4; ni++) {
            int p = nB + ni*8 + 2*(lane & 3);
            float* yp = &g_y[(size_t)l*DIN + h*HD + p];
            const float* xb = &g_xBC[(size_t)l*CONVD + h*HD + p];
            yp[0] += acc[ni][half*2]   * dec + xb[0]*dsk;
            yp[1] += acc[ni][half*2+1] * dec + xb[1]*dsk;
        }
    }
}

// ---------------- launch ----------------
extern "C" void kernel_launch(void* const* d_in, const int* in_sizes, int n_in,
                              void* d_out, int out_size) {
    const int*   ids  = (const int*)  d_in[0];
    const float* emb  = (const float*)d_in[1];
    const float* inw  = (const float*)d_in[2];
    const float* cw   = (const float*)d_in[3];
    const float* cb   = (const float*)d_in[4];
    const float* dtb  = (const float*)d_in[5];
    const float* alog = (const float*)d_in[6];
    const float* Dp   = (const float*)d_in[7];
    const float* mnw  = (const float*)d_in[8];
    const float* ow   = (const float*)d_in[9];
    const float* lnw  = (const float*)d_in[10];
    const float* nfw  = (const float*)d_in[11];
    float* out = (float*)d_out;

    float *px, *pzx;
    __nv_bfloat16 *pinwh, *pinwl, *puh, *pul;
    __half *powh16, *powl16, *pyn16, *pembh, *pu16;
    cudaGetSymbolAddress((void**)&px,    g_x);
    cudaGetSymbolAddress((void**)&pzx,   g_zx);
    cudaGetSymbolAddress((void**)&pinwh, g_inwh);
    cudaGetSymbolAddress((void**)&pinwl, g_inwl);
    cudaGetSymbolAddress((void**)&puh,   g_uh);
    cudaGetSymbolAddress((void**)&pul,   g_ul);
    cudaGetSymbolAddress((void**)&powh16, g_owh16);
    cudaGetSymbolAddress((void**)&powl16, g_owl16);
    cudaGetSymbolAddress((void**)&pyn16, g_yn16);
    cudaGetSymbolAddress((void**)&pembh, g_embh);
    cudaGetSymbolAddress((void**)&pu16,  g_u16);

    cudaFuncSetAttribute(gemm_tc,      cudaFuncAttributeMaxDynamicSharedMemorySize, GEMM_SMEM);
    cudaFuncSetAttribute(gemm_half,    cudaFuncAttributeMaxDynamicSharedMemorySize, GEMMH_SMEM);
    cudaFuncSetAttribute(gemm_half2,   cudaFuncAttributeMaxDynamicSharedMemorySize, GEMM2_SMEM);
    cudaFuncSetAttribute(cb_kernel,    cudaFuncAttributeMaxDynamicSharedMemorySize, CB_SMEM);
    cudaFuncSetAttribute(chunk_kernel, cudaFuncAttributeMaxDynamicSharedMemorySize, CHUNK_SMEM);
    cudaFuncSetAttribute(yoff_kernel,  cudaFuncAttributeMaxDynamicSharedMemorySize, YOFF_SMEM);

    // weight prep
    convert_half_kernel<<<(NV*DM/4 + 255)/256, 256>>>(emb, pembh, NV*DM/4);
    split_kernel<<<(NL*DPROJ*DM/4 + 255)/256, 256>>>(inw, pinwh, pinwl, NL*DPROJ*DM/4);
    split_half_kernel<<<(NL*DM*DIN + 255)/256, 256>>>(ow, powh16, powl16, NL*DM*DIN);

    embed_kernel<<<SEQ, 256>>>(ids, emb);

    for (int i = 0; i < NL; i++) {
        rmsnorm_split_kernel<<<SEQ, 256>>>(px, lnw + (size_t)i*DM, puh, pul);
        gemm_tc<<<dim3(SEQ/128, (DPROJ + 127)/128), 256, GEMM_SMEM>>>(
            puh, pul, pinwh + (size_t)i*DPROJ*DM, pinwl + (size_t)i*DPROJ*DM,
            pzx, SEQ, DPROJ, DM);
        conv_dtacs_kernel<<<CONV_BLKS + 96, 256>>>(
            cw + (size_t)i*CONVD*4, cb + (size_t)i*CONVD, dtb + i*NH, alog + i*NH);
        cb_kernel<<<NCH, 256, CB_SMEM>>>();
        chunk_kernel<<<dim3(NCH, NH), 256, CHUNK_SMEM>>>();
        scan_kernel<<<NH*HD*DSTATE/256, 256>>>();
        yoff_kernel<<<dim3(NCH, NH), 256, YOFF_SMEM>>>(Dp + i*NH);
        gated_rmsnorm_kernel<<<SEQ, 256>>>(mnw + (size_t)i*DIN);
        gemm_half2<<<dim3(SEQ/128, DM/128), 256, GEMM2_SMEM>>>(
            pyn16, powh16 + (size_t)i*DM*DIN, powl16 + (size_t)i*DM*DIN,
            px, px, SEQ, DM, DIN);
    }

    rmsnorm_half_kernel<<<SEQ, 256>>>(px, nfw, pu16);
    gemm_half<<<dim3(SEQ/128, (NV + 127)/128), 256, GEMMH_SMEM>>>(
        pu16, pembh, out, SEQ, NV, DM);
}